// round 8
// baseline (speedup 1.0000x reference)
#include <cuda_runtime.h>
#include <cstddef>
#include <cstdint>

// Problem constants
#define BB   128     // batch
#define TT   512     // seq len
#define EE   256     // embed dim
#define HH   256     // hidden
#define G4H  1024    // 4*H
#define VV   32000   // vocab
#define NC   32      // classes

typedef unsigned long long ull;

// ---------------- device scratch (no allocations allowed) ----------------
__device__ float g_P[(size_t)VV * 2048];       // [V][2*4H] vocab projection
__device__ ull   g_hxd[16][HH][16];            // [group][hcol][row] DUPLICATED h pairs (single buf)
__device__ float g_hfinT[2][HH][BB];           // final hidden per direction, transposed
__device__ int   g_flag[16][8][32];            // per-(group,CTA) release flags, 128B lines

// ---------------- f32x2 helpers ----------------
__device__ __forceinline__ ull pack2(float lo, float hi) {
    ull r;
    asm("mov.b64 %0, {%1, %2};" : "=l"(r) : "f"(lo), "f"(hi));
    return r;
}
__device__ __forceinline__ float2 unpack2(ull v) {
    float2 r;
    asm("mov.b64 {%0, %1}, %2;" : "=f"(r.x), "=f"(r.y) : "l"(v));
    return r;
}
__device__ __forceinline__ void ffma2(ull& d, ull a, ull b) {
    asm("fma.rn.f32x2 %0, %1, %2, %0;" : "+l"(d) : "l"(a), "l"(b));
}

__device__ __forceinline__ int ld_acq(const int* p) {
    int v;
    asm volatile("ld.acquire.gpu.b32 %0, [%1];" : "=r"(v) : "l"(p));
    return v;
}
__device__ __forceinline__ void st_rel(int* p, int v) {
    asm volatile("st.release.gpu.b32 [%0], %1;" :: "l"(p), "r"(v) : "memory");
}

__device__ __forceinline__ float sigm(float x) { return 1.0f / (1.0f + expf(-x)); }

__device__ __forceinline__ void cpasync16(uint32_t dst, const void* src) {
    asm volatile("cp.async.cg.shared.global [%0], [%1], 16;" :: "r"(dst), "l"(src) : "memory");
}
__device__ __forceinline__ void cp_commit() {
    asm volatile("cp.async.commit_group;" ::: "memory");
}
template<int N> __device__ __forceinline__ void cp_wait() {
    asm volatile("cp.async.wait_group %0;" :: "n"(N) : "memory");
}

// =====================================================================
// Kernel A: P[v, d*1024+g] = sum_e emb[v,e] * W{f,b}[e,g] + b{f,b}[g]
// (unchanged — measured 870us) Also resets the exchange flags.
// =====================================================================
__global__ void __launch_bounds__(256) proj_kernel(
    const float* __restrict__ emb,
    const float* __restrict__ Wf, const float* __restrict__ bf,
    const float* __restrict__ Wb, const float* __restrict__ bb)
{
    if (blockIdx.x == 0 && blockIdx.y == 0 && threadIdx.x < 128)
        g_flag[threadIdx.x >> 3][threadIdx.x & 7][0] = 0;

    __shared__ ull   Ad[16][66];   // dup'd A; row stride 528 B (16B-aligned rows)
    __shared__ float Bs[16][64];

    const int tid = threadIdx.x;
    const int tx = tid & 15, ty = tid >> 4;
    const int m0 = ty * 4, n0 = tx * 4;
    const int vbase = blockIdx.y * 64;
    const int nbase = blockIdx.x * 64;
    const int d = nbase >> 10;
    const float* W    = d ? Wb : Wf;
    const float* bias = d ? bb : bf;
    const int gbase = nbase & 1023;

    ull acc[4][2] = {};

    for (int kt = 0; kt < 256; kt += 16) {
        #pragma unroll
        for (int i = tid; i < 1024; i += 256) {
            int row = i >> 4, k = i & 15;
            float v = emb[(size_t)(vbase + row) * EE + kt + k];
            Ad[k][row] = pack2(v, v);
        }
        #pragma unroll
        for (int i = tid; i < 1024; i += 256) {
            int k = i >> 6, c = i & 63;
            Bs[k][c] = W[(size_t)(kt + k) * G4H + gbase + c];
        }
        __syncthreads();
        #pragma unroll
        for (int k = 0; k < 16; k++) {
            ulonglong2 a01 = *(const ulonglong2*)&Ad[k][m0];
            ulonglong2 a23 = *(const ulonglong2*)&Ad[k][m0 + 2];
            ulonglong2 bb2 = *(const ulonglong2*)&Bs[k][n0];
            ffma2(acc[0][0], a01.x, bb2.x);
            ffma2(acc[0][1], a01.x, bb2.y);
            ffma2(acc[1][0], a01.y, bb2.x);
            ffma2(acc[1][1], a01.y, bb2.y);
            ffma2(acc[2][0], a23.x, bb2.x);
            ffma2(acc[2][1], a23.x, bb2.y);
            ffma2(acc[3][0], a23.y, bb2.x);
            ffma2(acc[3][1], a23.y, bb2.y);
        }
        __syncthreads();
    }

    #pragma unroll
    for (int i = 0; i < 4; i++) {
        int v = vbase + m0 + i;
        #pragma unroll
        for (int p = 0; p < 2; p++) {
            float2 va = unpack2(acc[i][p]);
            int c = n0 + 2 * p;
            va.x += bias[gbase + c];
            va.y += bias[gbase + c + 1];
            *(float2*)&g_P[(size_t)v * 2048 + nbase + c] = va;
        }
    }
}

// =====================================================================
// Kernel B: batch-partitioned bidirectional LSTM, release/acquire exchange.
//
// Group = (direction, 16-row batch block); 16 groups x 8 CTAs.
// CTA rank c owns h-cols [c*32, c*32+32). Thread (j = tid>>3, rp = tid&7):
// tile = hcol j x 4 gates x rows (2rp, 2rp+1); gates packed in f32x2 accums.
// SMEM: Up[k][j] = ulonglong2{(u_i,u_f),(u_g,u_o)}  (128 KB, non-dup)
//       hd[k][row] = dup'd h pairs (32 KB, SINGLE buffer)
// Inner loop per warp per k: 2 x LDS.128 + 4 FFMA2 -> 16 cyc/k floor.
// Exchange: STG publish -> bar -> tid0 st.release flag -> all threads
// acquire-poll peer flags in parallel -> bar -> own slice STS + 28KB cp.async.
// =====================================================================
#define UP_U2S   (256 * 32)                         // ulonglong2 count, 128 KB
#define HD_ULLS  (256 * 16)                         // 32 KB
#define LSTM_SMEM_BYTES (UP_U2S * 16 + HD_ULLS * 8)   // 160 KB

__global__ void __launch_bounds__(256) lstm_kernel(
    const int* __restrict__ tokens,
    const float* __restrict__ Uf, const float* __restrict__ Ub)
{
    extern __shared__ char smraw[];
    ulonglong2* Up = (ulonglong2*)smraw;                  // [256 k][32 j]
    ull* hd = (ull*)(smraw + UP_U2S * 16);                // [256 k][16 row]
    const uint32_t hd_addr = (uint32_t)__cvta_generic_to_shared(hd);

    const int tid = threadIdx.x;
    const int gr  = blockIdx.x >> 3;              // group 0..15
    const int c   = blockIdx.x & 7;               // rank in group
    const int d   = gr >> 3;                      // direction
    const int rb  = (gr & 7) * 16;                // batch row base
    const float* U = d ? Ub : Uf;

    const int j  = tid >> 3;                      // hcol within CTA (0..31)
    const int rp = tid & 7;                       // row pair (rows 2rp, 2rp+1)

    // Token dtype guard (jnp.int64 silently x32 in JAX unless x64 enabled).
    const bool is64 = ((tokens[1] | tokens[3] | tokens[5] | tokens[7]) == 0);
    const int ts = is64 ? 2 : 1;

    // Load U: Up[k][jj] = { (u_i, u_f), (u_g, u_o) } at hcol c*32+jj
    for (int i = tid; i < 8192; i += 256) {
        int k = i >> 5, jj = i & 31;
        const float* ub = U + (size_t)k * G4H + c * 32 + jj;
        ulonglong2 e;
        e.x = pack2(ub[0],   ub[256]);
        e.y = pack2(ub[512], ub[768]);
        Up[k * 32 + jj] = e;
    }
    // zero h buffer (h(-1) = 0)
    for (int i = tid; i < HD_ULLS; i += 256) hd[i] = 0ull;
    __syncthreads();

    const int r0 = rb + 2 * rp;                   // global rows r0, r0+1
    const int* tokRow0 = tokens + (size_t)r0 * TT * ts;
    const int* tokRow1 = tokens + (size_t)(r0 + 1) * TT * ts;

    const int* peerflag = &g_flag[gr][tid & 7][0];
    int* myflag = &g_flag[gr][c][0];

    // prefetch tokens for t = 0
    int te0 = d ? (TT - 1) : 0;
    int tokA = tokRow0[te0 * ts];
    int tokB = tokRow1[te0 * ts];

    float cs0 = 0.f, cs1 = 0.f;

    for (int t = 0; t < TT; t++) {
        int tA = (tokA >= 0 && tokA < VV) ? tokA : 0;
        int tB = (tokB >= 0 && tokB < VV) ? tokB : 0;

        // input-projection loads (consumed after k-loop; latency hidden)
        const float* PA = g_P + (size_t)tA * 2048 + d * 1024 + c * 32 + j;
        const float* PB = g_P + (size_t)tB * 2048 + d * 1024 + c * 32 + j;
        float pA0 = PA[0], pA1 = PA[256], pA2 = PA[512], pA3 = PA[768];
        float pB0 = PB[0], pB1 = PB[256], pB2 = PB[512], pB3 = PB[768];

        // prefetch tokens for t+1
        if (t + 1 < TT) {
            int te = d ? (TT - 2 - t) : (t + 1);
            tokA = tokRow0[te * ts];
            tokB = tokRow1[te * ts];
        }

        // z = h(t-1) . U over k=256; per warp per k: 2 LDS.128 + 4 FFMA2
        const ulonglong2* up = Up + j;
        const ull* hb = hd + 2 * rp;
        ull aA = 0, aB = 0, aC = 0, aD = 0;
        #pragma unroll 8
        for (int k = 0; k < HH; k++) {
            ulonglong2 u = up[k * 32];
            ulonglong2 hv = *(const ulonglong2*)(hb + k * 16);
            ffma2(aA, hv.x, u.x);
            ffma2(aB, hv.x, u.y);
            ffma2(aC, hv.y, u.x);
            ffma2(aD, hv.y, u.y);
        }

        float2 vA = unpack2(aA), vB = unpack2(aB);
        float2 vC = unpack2(aC), vD = unpack2(aD);
        float i0 = sigm(vA.x + pA0), f0 = sigm(vA.y + pA1);
        float g0 = tanhf(vB.x + pA2), o0 = sigm(vB.y + pA3);
        float i1 = sigm(vC.x + pB0), f1 = sigm(vC.y + pB1);
        float g1 = tanhf(vD.x + pB2), o1 = sigm(vD.y + pB3);
        cs0 = f0 * cs0 + i0 * g0;
        cs1 = f1 * cs1 + i1 * g1;
        float h0 = o0 * tanhf(cs0);
        float h1 = o1 * tanhf(cs1);

        if (t == TT - 1) {
            g_hfinT[d][c * 32 + j][r0]     = h0;
            g_hfinT[d][c * 32 + j][r0 + 1] = h1;
        } else {
            // publish pre-duplicated h pairs: one aligned STG.128
            ulonglong2 outv;
            outv.x = pack2(h0, h0);
            outv.y = pack2(h1, h1);
            *(ulonglong2*)&g_hxd[gr][c * 32 + j][2 * rp] = outv;

            __syncthreads();                       // all CTA stores issued
            if (tid == 0) st_rel(myflag, t + 1);   // CG-style release publish

            // parallel acquire-poll: thread i watches peer (tid&7)
            while (ld_acq(peerflag) < t + 1) { }
            __syncthreads();                       // collective acquire

            // own slice direct to SMEM (no global round trip)
            *(ulonglong2*)(hd + (c * 32 + j) * 16 + 2 * rp) = outv;

            // stage 7 peer slices (28 KB) via cp.async
            const char* src = (const char*)&g_hxd[gr][0][0];
            #pragma unroll
            for (int q = 0; q < 7; q++) {
                int i = tid + q * 256;
                int blk = i >> 8;
                int peer = blk + (blk >= c ? 1 : 0);
                uint32_t off = (uint32_t)(peer * 4096 + (i & 255) * 16);
                cpasync16(hd_addr + off, src + off);
            }
            cp_commit();
            cp_wait<0>();
            __syncthreads();                       // hd = h(t) complete
        }
    }
}

// =====================================================================
// Kernel C: head.  h1 = relu([hf|hb] @ W1 + b1); out = softmax(h1 @ W2 + b2)
// =====================================================================
__global__ void __launch_bounds__(256) head_kernel(
    const float* __restrict__ W1, const float* __restrict__ b1,
    const float* __restrict__ W2, const float* __restrict__ b2,
    float* __restrict__ out)
{
    __shared__ float hc[8][512];
    __shared__ float h1[8][256];

    const int tid = threadIdx.x;
    const int rb = blockIdx.x * 8;

    for (int i = tid; i < 4096; i += 256) {
        int rr = i >> 9, k = i & 511;
        int dd = k >> 8, kk = k & 255;
        hc[rr][k] = g_hfinT[dd][kk][rb + rr];
    }
    __syncthreads();

    const int jj = tid;
    float acc[8] = {0.f, 0.f, 0.f, 0.f, 0.f, 0.f, 0.f, 0.f};
    for (int k = 0; k < 512; k++) {
        float w = W1[(size_t)k * HH + jj];
        #pragma unroll
        for (int rr = 0; rr < 8; rr++) acc[rr] += hc[rr][k] * w;
    }
    float bj = b1[jj];
    #pragma unroll
    for (int rr = 0; rr < 8; rr++) h1[rr][jj] = fmaxf(acc[rr] + bj, 0.f);
    __syncthreads();

    const int rr = tid >> 5, cc = tid & 31;
    float l = b2[cc];
    for (int k = 0; k < HH; k++) l += h1[rr][k] * W2[(size_t)k * NC + cc];

    float m = l;
    #pragma unroll
    for (int o = 16; o > 0; o >>= 1) m = fmaxf(m, __shfl_xor_sync(0xffffffffu, m, o));
    float e = expf(l - m);
    float ssum = e;
    #pragma unroll
    for (int o = 16; o > 0; o >>= 1) ssum += __shfl_xor_sync(0xffffffffu, ssum, o);
    out[(size_t)(rb + rr) * NC + cc] = e / ssum;
}

// =====================================================================
extern "C" void kernel_launch(void* const* d_in, const int* in_sizes, int n_in,
                              void* d_out, int out_size)
{
    const int*   tokens = (const int*)d_in[0];
    const float* emb = (const float*)d_in[1];
    const float* Wf  = (const float*)d_in[2];
    const float* Uf  = (const float*)d_in[3];
    const float* bf  = (const float*)d_in[4];
    const float* Wb  = (const float*)d_in[5];
    const float* Ub  = (const float*)d_in[6];
    const float* bb  = (const float*)d_in[7];
    const float* W1  = (const float*)d_in[8];
    const float* b1  = (const float*)d_in[9];
    const float* W2  = (const float*)d_in[10];
    const float* b2  = (const float*)d_in[11];
    float* out = (float*)d_out;

    cudaFuncSetAttribute(lstm_kernel, cudaFuncAttributeMaxDynamicSharedMemorySize, LSTM_SMEM_BYTES);

    proj_kernel<<<dim3(32, 500), 256>>>(emb, Wf, bf, Wb, bb);
    lstm_kernel<<<128, 256, LSTM_SMEM_BYTES>>>(tokens, Uf, Ub);
    head_kernel<<<16, 256>>>(W1, b1, W2, b2, out);
}

// round 9
// speedup vs baseline: 1.2553x; 1.2553x over previous
#include <cuda_runtime.h>
#include <cstddef>
#include <cstdint>

// Problem constants
#define BB   128     // batch
#define TT   512     // seq len
#define EE   256     // embed dim
#define HH   256     // hidden
#define G4H  1024    // 4*H
#define VV   32000   // vocab
#define NC   32      // classes

typedef unsigned long long ull;

// ---------------- device scratch (no allocations allowed) ----------------
__device__ float g_P[(size_t)VV * 2048];       // [V][2*4H] vocab projection
__device__ float g_hx[16][2][HH][16];          // [group][buf][hcol][row] h exchange (non-dup)
__device__ float g_hfinT[2][HH][BB];           // final hidden per direction, transposed
__device__ int   g_ctr[16 * 32];               // per-group barrier counters (128B apart)

// ---------------- f32x2 helpers ----------------
__device__ __forceinline__ ull pack2(float lo, float hi) {
    ull r;
    asm("mov.b64 %0, {%1, %2};" : "=l"(r) : "f"(lo), "f"(hi));
    return r;
}
__device__ __forceinline__ float2 unpack2(ull v) {
    float2 r;
    asm("mov.b64 {%0, %1}, %2;" : "=f"(r.x), "=f"(r.y) : "l"(v));
    return r;
}
__device__ __forceinline__ void ffma2(ull& d, ull a, ull b) {
    asm("fma.rn.f32x2 %0, %1, %2, %0;" : "+l"(d) : "l"(a), "l"(b));
}
__device__ __forceinline__ void addf2(ull& d, ull a) {
    asm("add.rn.f32x2 %0, %0, %1;" : "+l"(d) : "l"(a));
}

__device__ __forceinline__ int ld_acq(const int* p) {
    int v;
    asm volatile("ld.acquire.gpu.b32 %0, [%1];" : "=r"(v) : "l"(p));
    return v;
}

__device__ __forceinline__ float sigm(float x) { return 1.0f / (1.0f + expf(-x)); }

__device__ __forceinline__ void cpasync16(uint32_t dst, const void* src) {
    asm volatile("cp.async.cg.shared.global [%0], [%1], 16;" :: "r"(dst), "l"(src) : "memory");
}
__device__ __forceinline__ void cp_commit() {
    asm volatile("cp.async.commit_group;" ::: "memory");
}
template<int N> __device__ __forceinline__ void cp_wait() {
    asm volatile("cp.async.wait_group %0;" :: "n"(N) : "memory");
}

// =====================================================================
// Kernel A: P[v, d*1024+g] = sum_e emb[v,e] * W{f,b}[e,g] + b{f,b}[g]
// (unchanged — measured 870us) Also resets group barrier counters.
// =====================================================================
__global__ void __launch_bounds__(256) proj_kernel(
    const float* __restrict__ emb,
    const float* __restrict__ Wf, const float* __restrict__ bf,
    const float* __restrict__ Wb, const float* __restrict__ bb)
{
    if (blockIdx.x == 0 && blockIdx.y == 0 && threadIdx.x < 16)
        g_ctr[threadIdx.x * 32] = 0;

    __shared__ ull   Ad[16][66];   // dup'd A; row stride 528 B (16B-aligned rows)
    __shared__ float Bs[16][64];

    const int tid = threadIdx.x;
    const int tx = tid & 15, ty = tid >> 4;
    const int m0 = ty * 4, n0 = tx * 4;
    const int vbase = blockIdx.y * 64;
    const int nbase = blockIdx.x * 64;
    const int d = nbase >> 10;
    const float* W    = d ? Wb : Wf;
    const float* bias = d ? bb : bf;
    const int gbase = nbase & 1023;

    ull acc[4][2] = {};

    for (int kt = 0; kt < 256; kt += 16) {
        #pragma unroll
        for (int i = tid; i < 1024; i += 256) {
            int row = i >> 4, k = i & 15;
            float v = emb[(size_t)(vbase + row) * EE + kt + k];
            Ad[k][row] = pack2(v, v);
        }
        #pragma unroll
        for (int i = tid; i < 1024; i += 256) {
            int k = i >> 6, cc = i & 63;
            Bs[k][cc] = W[(size_t)(kt + k) * G4H + gbase + cc];
        }
        __syncthreads();
        #pragma unroll
        for (int k = 0; k < 16; k++) {
            ulonglong2 a01 = *(const ulonglong2*)&Ad[k][m0];
            ulonglong2 a23 = *(const ulonglong2*)&Ad[k][m0 + 2];
            ulonglong2 bb2 = *(const ulonglong2*)&Bs[k][n0];
            ffma2(acc[0][0], a01.x, bb2.x);
            ffma2(acc[0][1], a01.x, bb2.y);
            ffma2(acc[1][0], a01.y, bb2.x);
            ffma2(acc[1][1], a01.y, bb2.y);
            ffma2(acc[2][0], a23.x, bb2.x);
            ffma2(acc[2][1], a23.x, bb2.y);
            ffma2(acc[3][0], a23.y, bb2.x);
            ffma2(acc[3][1], a23.y, bb2.y);
        }
        __syncthreads();
    }

    #pragma unroll
    for (int i = 0; i < 4; i++) {
        int v = vbase + m0 + i;
        #pragma unroll
        for (int p = 0; p < 2; p++) {
            float2 va = unpack2(acc[i][p]);
            int cc = n0 + 2 * p;
            va.x += bias[gbase + cc];
            va.y += bias[gbase + cc + 1];
            *(float2*)&g_P[(size_t)v * 2048 + nbase + cc] = va;
        }
    }
}

// =====================================================================
// Kernel B: register-tiled k-split LSTM.
//
// 16 groups (dir x 16-row block) x 8 CTAs; CTA rank c owns hcols [32c,32c+32).
// 128 threads = 4 warps. Warp w owns k-slice [64w, 64w+64).
// Lane (rg = lane&3: rows 4rg.., cg = lane>>2: hcols 4cg..) covers ALL
// 16r x 32hcol x 4g of the CTA within its k-slice.
// Thread tile: 4 rows x 4 hcols x 4 gates = 32 f32x2 accums.
// Per k per thread: 1 LDS.128 raw h + 4 movs (dup) + 4 LDS.128 U + 32 FFMA2.
// Crossbar: 5 LDS.128/warp-k -> 5120 cyc/step; FMA floor 4096/SMSP.
// Then 4-way k-reduction via padded SMEM, activation on final tile
// (4 rows x 1 hcol per thread), R7 exchange protocol (atomic group barrier,
// deferred cp.async wait).
// =====================================================================
#define UP_BYTES   131072                      // [256 k][32 j] ulonglong2
#define HR_BYTES   32768                       // [2 buf][256 k][16 row] float
#define RED_STRIDE 34                          // ull per reduction row (pad)
#define RED_BYTES  (4 * 32 * RED_STRIDE * 8)   // 34816
#define LSTM_SMEM_BYTES (UP_BYTES + HR_BYTES + RED_BYTES)   // 198656

__global__ void __launch_bounds__(128) lstm_kernel(
    const int* __restrict__ tokens,
    const float* __restrict__ Uf, const float* __restrict__ Ub)
{
    extern __shared__ char smraw[];
    ulonglong2* Up = (ulonglong2*)smraw;                     // [256 k][32 j]
    float* hraw = (float*)(smraw + UP_BYTES);                // [2][256][16]
    ull* red = (ull*)(smraw + UP_BYTES + HR_BYTES);          // [4][32][34]
    const uint32_t hraw_addr = (uint32_t)__cvta_generic_to_shared(hraw);

    const int tid = threadIdx.x;
    const int gr  = blockIdx.x >> 3;              // group 0..15
    const int c   = blockIdx.x & 7;               // rank in group
    const int d   = gr >> 3;                      // direction
    const int rb  = (gr & 7) * 16;                // batch row base
    const float* U = d ? Ub : Uf;

    const int w    = tid >> 5;                    // warp = k-slice = row-quad owner
    const int lane = tid & 31;
    const int rg   = lane & 3;                    // row group (rows 4rg..4rg+3)
    const int cg   = lane >> 2;                   // hcol group (hcols 4cg..4cg+3)

    // final-tile identity (post-reduction): hcol jloc, rows 4q..4q+3
    const int jloc = tid & 31;
    const int q    = tid >> 5;
    const int ghcol = c * 32 + jloc;

    // Token dtype guard (jnp.int64 silently x32 in JAX unless x64 enabled).
    const bool is64 = ((tokens[1] | tokens[3] | tokens[5] | tokens[7]) == 0);
    const int ts = is64 ? 2 : 1;

    // Load U: Up[k][jj] = { (u_i, u_f), (u_g, u_o) } at hcol c*32+jj
    for (int i = tid; i < 8192; i += 128) {
        int k = i >> 5, jj = i & 31;
        const float* ub = U + (size_t)k * G4H + c * 32 + jj;
        ulonglong2 e;
        e.x = pack2(ub[0],   ub[256]);
        e.y = pack2(ub[512], ub[768]);
        Up[k * 32 + jj] = e;
    }
    // zero h buffer 0 (h(-1) = 0)
    for (int i = tid; i < 4096; i += 128) hraw[i] = 0.f;
    __syncthreads();

    // token row pointers for final-tile rows rb+4q+r
    const int* tr0 = tokens + (size_t)(rb + 4 * q + 0) * TT * ts;
    const int* tr1 = tokens + (size_t)(rb + 4 * q + 1) * TT * ts;
    const int* tr2 = tokens + (size_t)(rb + 4 * q + 2) * TT * ts;
    const int* tr3 = tokens + (size_t)(rb + 4 * q + 3) * TT * ts;

    int* ctr = &g_ctr[gr * 32];

    // prefetch tokens for t = 0
    int te0 = d ? (TT - 1) : 0;
    int tk0 = tr0[te0 * ts], tk1 = tr1[te0 * ts];
    int tk2 = tr2[te0 * ts], tk3 = tr3[te0 * ts];

    float cs[4] = {0.f, 0.f, 0.f, 0.f};

    for (int t = 0; t < TT; t++) {
        const int buf = t & 1;

        // ---- issue P loads for this step (consumed post-reduction) ----
        int tv0 = (tk0 >= 0 && tk0 < VV) ? tk0 : 0;
        int tv1 = (tk1 >= 0 && tk1 < VV) ? tk1 : 0;
        int tv2 = (tk2 >= 0 && tk2 < VV) ? tk2 : 0;
        int tv3 = (tk3 >= 0 && tk3 < VV) ? tk3 : 0;
        const float* Pb0 = g_P + (size_t)tv0 * 2048 + d * 1024 + ghcol;
        const float* Pb1 = g_P + (size_t)tv1 * 2048 + d * 1024 + ghcol;
        const float* Pb2 = g_P + (size_t)tv2 * 2048 + d * 1024 + ghcol;
        const float* Pb3 = g_P + (size_t)tv3 * 2048 + d * 1024 + ghcol;
        float p00 = Pb0[0], p01 = Pb0[256], p02 = Pb0[512], p03 = Pb0[768];
        float p10 = Pb1[0], p11 = Pb1[256], p12 = Pb1[512], p13 = Pb1[768];
        float p20 = Pb2[0], p21 = Pb2[256], p22 = Pb2[512], p23 = Pb2[768];
        float p30 = Pb3[0], p31 = Pb3[256], p32 = Pb3[512], p33 = Pb3[768];

        // prefetch tokens for t+1
        if (t + 1 < TT) {
            int te = d ? (TT - 2 - t) : (t + 1);
            tk0 = tr0[te * ts]; tk1 = tr1[te * ts];
            tk2 = tr2[te * ts]; tk3 = tr3[te * ts];
        }

        if (t > 0) { cp_wait<0>(); __syncthreads(); }   // h(t-1) staged

        // ---- k-loop over this warp's slice ----
        const float* hb = hraw + buf * 4096;
        const ulonglong2* upb = Up + 4 * cg;
        ull aIF[4][4] = {}, aGO[4][4] = {};
        const int kbeg = w * 64;
        #pragma unroll 4
        for (int k = kbeg; k < kbeg + 64; k++) {
            float4 hv = *(const float4*)(hb + k * 16 + 4 * rg);
            ull hd0 = pack2(hv.x, hv.x);
            ull hd1 = pack2(hv.y, hv.y);
            ull hd2 = pack2(hv.z, hv.z);
            ull hd3 = pack2(hv.w, hv.w);
            ulonglong2 u0 = upb[k * 32 + 0];
            ulonglong2 u1 = upb[k * 32 + 1];
            ulonglong2 u2 = upb[k * 32 + 2];
            ulonglong2 u3 = upb[k * 32 + 3];
            ffma2(aIF[0][0], hd0, u0.x); ffma2(aGO[0][0], hd0, u0.y);
            ffma2(aIF[0][1], hd0, u1.x); ffma2(aGO[0][1], hd0, u1.y);
            ffma2(aIF[0][2], hd0, u2.x); ffma2(aGO[0][2], hd0, u2.y);
            ffma2(aIF[0][3], hd0, u3.x); ffma2(aGO[0][3], hd0, u3.y);
            ffma2(aIF[1][0], hd1, u0.x); ffma2(aGO[1][0], hd1, u0.y);
            ffma2(aIF[1][1], hd1, u1.x); ffma2(aGO[1][1], hd1, u1.y);
            ffma2(aIF[1][2], hd1, u2.x); ffma2(aGO[1][2], hd1, u2.y);
            ffma2(aIF[1][3], hd1, u3.x); ffma2(aGO[1][3], hd1, u3.y);
            ffma2(aIF[2][0], hd2, u0.x); ffma2(aGO[2][0], hd2, u0.y);
            ffma2(aIF[2][1], hd2, u1.x); ffma2(aGO[2][1], hd2, u1.y);
            ffma2(aIF[2][2], hd2, u2.x); ffma2(aGO[2][2], hd2, u2.y);
            ffma2(aIF[2][3], hd2, u3.x); ffma2(aGO[2][3], hd2, u3.y);
            ffma2(aIF[3][0], hd3, u0.x); ffma2(aGO[3][0], hd3, u0.y);
            ffma2(aIF[3][1], hd3, u1.x); ffma2(aGO[3][1], hd3, u1.y);
            ffma2(aIF[3][2], hd3, u2.x); ffma2(aGO[3][2], hd3, u2.y);
            ffma2(aIF[3][3], hd3, u3.x); ffma2(aGO[3][3], hd3, u3.y);
        }

        // ---- k-reduction: write partials ----
        ull* myred = red + (w * 32 + lane) * RED_STRIDE;
        #pragma unroll
        for (int r = 0; r < 4; r++) {
            #pragma unroll
            for (int cc = 0; cc < 4; cc++) {
                ulonglong2 pr;
                pr.x = aIF[r][cc];
                pr.y = aGO[r][cc];
                *(ulonglong2*)(myred + (r * 4 + cc) * 2) = pr;
            }
        }
        __syncthreads();

        // ---- gather + sum 4 k-slices for final tile (hcol jloc, rows 4q+r) ----
        const int srcLane = (jloc >> 2) * 4 + q;
        const int cslot = jloc & 3;
        float h0v, h1v, h2v, h3v;
        #pragma unroll
        for (int r = 0; r < 4; r++) {
            ull zIF = 0ull, zGO = 0ull;
            #pragma unroll
            for (int w4 = 0; w4 < 4; w4++) {
                ulonglong2 p = *(const ulonglong2*)(red +
                    (w4 * 32 + srcLane) * RED_STRIDE + (r * 4 + cslot) * 2);
                addf2(zIF, p.x);
                addf2(zGO, p.y);
            }
            float2 vIF = unpack2(zIF), vGO = unpack2(zGO);
            float pi, pf, pg, po;
            if (r == 0) { pi = p00; pf = p01; pg = p02; po = p03; }
            else if (r == 1) { pi = p10; pf = p11; pg = p12; po = p13; }
            else if (r == 2) { pi = p20; pf = p21; pg = p22; po = p23; }
            else { pi = p30; pf = p31; pg = p32; po = p33; }
            float iv = sigm(vIF.x + pi);
            float fv = sigm(vIF.y + pf);
            float gv = tanhf(vGO.x + pg);
            float ov = sigm(vGO.y + po);
            cs[r] = fv * cs[r] + iv * gv;
            float hv = ov * tanhf(cs[r]);
            if (r == 0) h0v = hv; else if (r == 1) h1v = hv;
            else if (r == 2) h2v = hv; else h3v = hv;
        }

        if (t == TT - 1) {
            *(float4*)&g_hfinT[d][ghcol][rb + 4 * q] = make_float4(h0v, h1v, h2v, h3v);
        } else {
            const int nb = buf ^ 1;
            // publish: one STG.128 per thread (non-dup, [hcol][row] layout)
            *(float4*)&g_hx[gr][nb][ghcol][4 * q] = make_float4(h0v, h1v, h2v, h3v);
            __threadfence();
            __syncthreads();
            if (tid == 0) {
                atomicAdd(ctr, 1);
                const int target = 8 * (t + 1);
                while (ld_acq(ctr) < target) { }
            }
            __syncthreads();
            // stage full group h(t) (16 KB) into SMEM buffer nb
            const char* src = (const char*)&g_hx[gr][nb][0][0];
            const uint32_t dbase = hraw_addr + (uint32_t)nb * 16384;
            #pragma unroll
            for (int qq = 0; qq < 8; qq++) {
                int f = tid + qq * 128;
                cpasync16(dbase + (uint32_t)f * 16, src + (size_t)f * 16);
            }
            cp_commit();
        }
    }
}

// =====================================================================
// Kernel C: head.  h1 = relu([hf|hb] @ W1 + b1); out = softmax(h1 @ W2 + b2)
// =====================================================================
__global__ void __launch_bounds__(256) head_kernel(
    const float* __restrict__ W1, const float* __restrict__ b1,
    const float* __restrict__ W2, const float* __restrict__ b2,
    float* __restrict__ out)
{
    __shared__ float hc[8][512];
    __shared__ float h1[8][256];

    const int tid = threadIdx.x;
    const int rb = blockIdx.x * 8;

    for (int i = tid; i < 4096; i += 256) {
        int rr = i >> 9, k = i & 511;
        int dd = k >> 8, kk = k & 255;
        hc[rr][k] = g_hfinT[dd][kk][rb + rr];
    }
    __syncthreads();

    const int jj = tid;
    float acc[8] = {0.f, 0.f, 0.f, 0.f, 0.f, 0.f, 0.f, 0.f};
    for (int k = 0; k < 512; k++) {
        float wv = W1[(size_t)k * HH + jj];
        #pragma unroll
        for (int rr = 0; rr < 8; rr++) acc[rr] += hc[rr][k] * wv;
    }
    float bj = b1[jj];
    #pragma unroll
    for (int rr = 0; rr < 8; rr++) h1[rr][jj] = fmaxf(acc[rr] + bj, 0.f);
    __syncthreads();

    const int rr = tid >> 5, cc = tid & 31;
    float l = b2[cc];
    for (int k = 0; k < HH; k++) l += h1[rr][k] * W2[(size_t)k * NC + cc];

    float m = l;
    #pragma unroll
    for (int o = 16; o > 0; o >>= 1) m = fmaxf(m, __shfl_xor_sync(0xffffffffu, m, o));
    float e = expf(l - m);
    float ssum = e;
    #pragma unroll
    for (int o = 16; o > 0; o >>= 1) ssum += __shfl_xor_sync(0xffffffffu, ssum, o);
    out[(size_t)(rb + rr) * NC + cc] = e / ssum;
}

// =====================================================================
extern "C" void kernel_launch(void* const* d_in, const int* in_sizes, int n_in,
                              void* d_out, int out_size)
{
    const int*   tokens = (const int*)d_in[0];
    const float* emb = (const float*)d_in[1];
    const float* Wf  = (const float*)d_in[2];
    const float* Uf  = (const float*)d_in[3];
    const float* bf  = (const float*)d_in[4];
    const float* Wb  = (const float*)d_in[5];
    const float* Ub  = (const float*)d_in[6];
    const float* bb  = (const float*)d_in[7];
    const float* W1  = (const float*)d_in[8];
    const float* b1  = (const float*)d_in[9];
    const float* W2  = (const float*)d_in[10];
    const float* b2  = (const float*)d_in[11];
    float* out = (float*)d_out;

    cudaFuncSetAttribute(lstm_kernel, cudaFuncAttributeMaxDynamicSharedMemorySize, LSTM_SMEM_BYTES);

    proj_kernel<<<dim3(32, 500), 256>>>(emb, Wf, bf, Wb, bb);
    lstm_kernel<<<128, 128, LSTM_SMEM_BYTES>>>(tokens, Uf, Ub);
    head_kernel<<<16, 256>>>(W1, b1, W2, b2, out);
}

// round 10
// speedup vs baseline: 1.3638x; 1.0864x over previous
#include <cuda_runtime.h>
#include <cstddef>
#include <cstdint>

// Problem constants
#define BB   128     // batch
#define TT   512     // seq len
#define EE   256     // embed dim
#define HH   256     // hidden
#define G4H  1024    // 4*H
#define VV   32000   // vocab
#define NC   32      // classes

typedef unsigned long long ull;

// ---------------- device scratch (no allocations allowed) ----------------
__device__ float g_P[(size_t)VV * 2048];       // [V][2*4H] vocab projection
__device__ float g_hx[16][2][HH][16];          // [group][buf][hcol][row] h exchange
__device__ float g_hfinT[2][HH][BB];           // final hidden per direction, transposed
__device__ int   g_ctr[16 * 32];               // per-group barrier counters (128B apart)

// ---------------- f32x2 helpers ----------------
__device__ __forceinline__ ull pack2(float lo, float hi) {
    ull r;
    asm("mov.b64 %0, {%1, %2};" : "=l"(r) : "f"(lo), "f"(hi));
    return r;
}
__device__ __forceinline__ float2 unpack2(ull v) {
    float2 r;
    asm("mov.b64 {%0, %1}, %2;" : "=f"(r.x), "=f"(r.y) : "l"(v));
    return r;
}
__device__ __forceinline__ void ffma2(ull& d, ull a, ull b) {
    asm("fma.rn.f32x2 %0, %1, %2, %0;" : "+l"(d) : "l"(a), "l"(b));
}
__device__ __forceinline__ void addf2(ull& d, ull a) {
    asm("add.rn.f32x2 %0, %0, %1;" : "+l"(d) : "l"(a));
}

__device__ __forceinline__ int ld_acq(const int* p) {
    int v;
    asm volatile("ld.acquire.gpu.b32 %0, [%1];" : "=r"(v) : "l"(p));
    return v;
}

__device__ __forceinline__ float sigm(float x) { return 1.0f / (1.0f + expf(-x)); }

__device__ __forceinline__ void cpasync16(uint32_t dst, const void* src) {
    asm volatile("cp.async.cg.shared.global [%0], [%1], 16;" :: "r"(dst), "l"(src) : "memory");
}
__device__ __forceinline__ void cp_commit() {
    asm volatile("cp.async.commit_group;" ::: "memory");
}
template<int N> __device__ __forceinline__ void cp_wait() {
    asm volatile("cp.async.wait_group %0;" :: "n"(N) : "memory");
}

// =====================================================================
// Kernel A: P[v, d*1024+g] = sum_e emb[v,e] * W{f,b}[e,g] + b{f,b}[g]
// (unchanged — measured 870us) Also resets group barrier counters.
// =====================================================================
__global__ void __launch_bounds__(256) proj_kernel(
    const float* __restrict__ emb,
    const float* __restrict__ Wf, const float* __restrict__ bf,
    const float* __restrict__ Wb, const float* __restrict__ bb)
{
    if (blockIdx.x == 0 && blockIdx.y == 0 && threadIdx.x < 16)
        g_ctr[threadIdx.x * 32] = 0;

    __shared__ ull   Ad[16][66];   // dup'd A; row stride 528 B (16B-aligned rows)
    __shared__ float Bs[16][64];

    const int tid = threadIdx.x;
    const int tx = tid & 15, ty = tid >> 4;
    const int m0 = ty * 4, n0 = tx * 4;
    const int vbase = blockIdx.y * 64;
    const int nbase = blockIdx.x * 64;
    const int d = nbase >> 10;
    const float* W    = d ? Wb : Wf;
    const float* bias = d ? bb : bf;
    const int gbase = nbase & 1023;

    ull acc[4][2] = {};

    for (int kt = 0; kt < 256; kt += 16) {
        #pragma unroll
        for (int i = tid; i < 1024; i += 256) {
            int row = i >> 4, k = i & 15;
            float v = emb[(size_t)(vbase + row) * EE + kt + k];
            Ad[k][row] = pack2(v, v);
        }
        #pragma unroll
        for (int i = tid; i < 1024; i += 256) {
            int k = i >> 6, cc = i & 63;
            Bs[k][cc] = W[(size_t)(kt + k) * G4H + gbase + cc];
        }
        __syncthreads();
        #pragma unroll
        for (int k = 0; k < 16; k++) {
            ulonglong2 a01 = *(const ulonglong2*)&Ad[k][m0];
            ulonglong2 a23 = *(const ulonglong2*)&Ad[k][m0 + 2];
            ulonglong2 bb2 = *(const ulonglong2*)&Bs[k][n0];
            ffma2(acc[0][0], a01.x, bb2.x);
            ffma2(acc[0][1], a01.x, bb2.y);
            ffma2(acc[1][0], a01.y, bb2.x);
            ffma2(acc[1][1], a01.y, bb2.y);
            ffma2(acc[2][0], a23.x, bb2.x);
            ffma2(acc[2][1], a23.x, bb2.y);
            ffma2(acc[3][0], a23.y, bb2.x);
            ffma2(acc[3][1], a23.y, bb2.y);
        }
        __syncthreads();
    }

    #pragma unroll
    for (int i = 0; i < 4; i++) {
        int v = vbase + m0 + i;
        #pragma unroll
        for (int p = 0; p < 2; p++) {
            float2 va = unpack2(acc[i][p]);
            int cc = n0 + 2 * p;
            va.x += bias[gbase + cc];
            va.y += bias[gbase + cc + 1];
            *(float2*)&g_P[(size_t)v * 2048 + nbase + cc] = va;
        }
    }
}

// =====================================================================
// Kernel B: register-tiled 8-way-k-split LSTM, conflict-clean layouts.
//
// 16 groups x 8 CTAs; CTA rank c owns hcols [32c, 32c+32).
// 256 threads = 8 warps; warp w owns k-slice [32w, 32w+32).
// Lane: rg = lane&1 (rows 8rg..8rg+7), cg = lane>>1 (hcols {cg, cg+16}).
// Thread tile: 8 rows x 2 hcols x 4 gates = 32 f32x2 accums.
// Per thread-k: 2 LDS.128 h (broadcast) + 2 LDS.128 U (16 contiguous
// 16B addrs -> <=2-way conflict, at 4-cyc floor) + 8 movs + 32 FFMA2.
// Crossbar floor = FMA floor = 4096 cyc/step (balanced).
// 8-way k-reduction in TWO passes (IF, GO) via 36KB padded SMEM.
// Final tile per thread: hcol jf = tid&31, rows {2q, 2q+1}, q = tid>>5.
// Exchange: R9 protocol (atomic group barrier + deferred cp.async).
// =====================================================================
#define UP_BYTES   131072                     // [256 k][32 hcol] ulonglong2
#define HR_BYTES   32768                      // [2 buf][256 k][16 row] float
#define RED_STRIDE 18                         // ull per thread row (16 + pad, 144B)
#define RED_BYTES  (256 * RED_STRIDE * 8)     // 36864
#define LSTM_SMEM_BYTES (UP_BYTES + HR_BYTES + RED_BYTES)   // 200704

__global__ void __launch_bounds__(256) lstm_kernel(
    const int* __restrict__ tokens,
    const float* __restrict__ Uf, const float* __restrict__ Ub)
{
    extern __shared__ char smraw[];
    ulonglong2* Up = (ulonglong2*)smraw;                     // [256 k][32 hcol]
    float* hraw = (float*)(smraw + UP_BYTES);                // [2][256][16]
    ull* red = (ull*)(smraw + UP_BYTES + HR_BYTES);          // [256 thr][18]
    const uint32_t hraw_addr = (uint32_t)__cvta_generic_to_shared(hraw);

    const int tid = threadIdx.x;
    const int gr  = blockIdx.x >> 3;              // group 0..15
    const int c   = blockIdx.x & 7;               // rank in group
    const int d   = gr >> 3;                      // direction
    const int rb  = (gr & 7) * 16;                // batch row base
    const float* U = d ? Ub : Uf;

    const int w    = tid >> 5;                    // warp -> k-slice [32w,32w+32)
    const int lane = tid & 31;
    const int rg   = lane & 1;                    // rows 8rg..8rg+7
    const int cg   = lane >> 1;                   // hcols {cg, cg+16}

    // final-tile identity (post-reduction)
    const int jf = tid & 31;                      // hcol within CTA
    const int q  = tid >> 5;                      // rows {2q, 2q+1}
    const int ghcol = c * 32 + jf;

    // Token dtype guard (jnp.int64 silently x32 in JAX unless x64 enabled).
    const bool is64 = ((tokens[1] | tokens[3] | tokens[5] | tokens[7]) == 0);
    const int ts = is64 ? 2 : 1;

    // Load U: Up[k][j] = { (u_i,u_f), (u_g,u_o) } at hcol c*32+j
    for (int i = tid; i < 8192; i += 256) {
        int k = i >> 5, j = i & 31;
        const float* ub = U + (size_t)k * G4H + c * 32 + j;
        ulonglong2 e;
        e.x = pack2(ub[0],   ub[256]);
        e.y = pack2(ub[512], ub[768]);
        Up[k * 32 + j] = e;
    }
    // zero both h buffers (h(-1) = 0)
    for (int i = tid; i < 8192; i += 256) hraw[i] = 0.f;
    __syncthreads();

    const int* tr0 = tokens + (size_t)(rb + 2 * q + 0) * TT * ts;
    const int* tr1 = tokens + (size_t)(rb + 2 * q + 1) * TT * ts;
    int* ctr = &g_ctr[gr * 32];

    // prefetch tokens for t = 0
    int te0 = d ? (TT - 1) : 0;
    int tk0 = tr0[te0 * ts], tk1 = tr1[te0 * ts];

    float cs0 = 0.f, cs1 = 0.f;

    // gather constants
    const int lane_src = 2 * (jf & 15) + (q >> 2);
    const int idx0 = ((2 * q) & 7) * 2 + (jf >> 4);

    for (int t = 0; t < TT; t++) {
        const int buf = t & 1;

        // ---- P loads for this step (consumed after reduction) ----
        int tv0 = (tk0 >= 0 && tk0 < VV) ? tk0 : 0;
        int tv1 = (tk1 >= 0 && tk1 < VV) ? tk1 : 0;
        const float* Pb0 = g_P + (size_t)tv0 * 2048 + d * 1024 + ghcol;
        const float* Pb1 = g_P + (size_t)tv1 * 2048 + d * 1024 + ghcol;
        float p00 = Pb0[0], p01 = Pb0[256], p02 = Pb0[512], p03 = Pb0[768];
        float p10 = Pb1[0], p11 = Pb1[256], p12 = Pb1[512], p13 = Pb1[768];

        // prefetch tokens for t+1
        if (t + 1 < TT) {
            int te = d ? (TT - 2 - t) : (t + 1);
            tk0 = tr0[te * ts]; tk1 = tr1[te * ts];
        }

        if (t > 0) { cp_wait<0>(); __syncthreads(); }   // h(t-1) staged

        // ---- k-loop over this warp's 32-k slice ----
        const float* hb = hraw + buf * 4096;
        const ulonglong2* ub2 = Up + cg;
        ull aIF[8][2] = {}, aGO[8][2] = {};
        const int kbeg = w * 32;
        #pragma unroll 4
        for (int k = kbeg; k < kbeg + 32; k++) {
            float4 hA = *(const float4*)(hb + k * 16 + 8 * rg);
            float4 hB = *(const float4*)(hb + k * 16 + 8 * rg + 4);
            ulonglong2 uA = ub2[k * 32];         // hcol cg
            ulonglong2 uB = ub2[k * 32 + 16];    // hcol cg+16
            ull hd0 = pack2(hA.x, hA.x), hd1 = pack2(hA.y, hA.y);
            ull hd2 = pack2(hA.z, hA.z), hd3 = pack2(hA.w, hA.w);
            ull hd4 = pack2(hB.x, hB.x), hd5 = pack2(hB.y, hB.y);
            ull hd6 = pack2(hB.z, hB.z), hd7 = pack2(hB.w, hB.w);
            ffma2(aIF[0][0], hd0, uA.x); ffma2(aGO[0][0], hd0, uA.y);
            ffma2(aIF[0][1], hd0, uB.x); ffma2(aGO[0][1], hd0, uB.y);
            ffma2(aIF[1][0], hd1, uA.x); ffma2(aGO[1][0], hd1, uA.y);
            ffma2(aIF[1][1], hd1, uB.x); ffma2(aGO[1][1], hd1, uB.y);
            ffma2(aIF[2][0], hd2, uA.x); ffma2(aGO[2][0], hd2, uA.y);
            ffma2(aIF[2][1], hd2, uB.x); ffma2(aGO[2][1], hd2, uB.y);
            ffma2(aIF[3][0], hd3, uA.x); ffma2(aGO[3][0], hd3, uA.y);
            ffma2(aIF[3][1], hd3, uB.x); ffma2(aGO[3][1], hd3, uB.y);
            ffma2(aIF[4][0], hd4, uA.x); ffma2(aGO[4][0], hd4, uA.y);
            ffma2(aIF[4][1], hd4, uB.x); ffma2(aGO[4][1], hd4, uB.y);
            ffma2(aIF[5][0], hd5, uA.x); ffma2(aGO[5][0], hd5, uA.y);
            ffma2(aIF[5][1], hd5, uB.x); ffma2(aGO[5][1], hd5, uB.y);
            ffma2(aIF[6][0], hd6, uA.x); ffma2(aGO[6][0], hd6, uA.y);
            ffma2(aIF[6][1], hd6, uB.x); ffma2(aGO[6][1], hd6, uB.y);
            ffma2(aIF[7][0], hd7, uA.x); ffma2(aGO[7][0], hd7, uA.y);
            ffma2(aIF[7][1], hd7, uB.x); ffma2(aGO[7][1], hd7, uB.y);
        }

        ull* myred = red + tid * RED_STRIDE;

        // ---- reduction pass 1: IF ----
        #pragma unroll
        for (int i = 0; i < 8; i++) {
            ulonglong2 pr; pr.x = aIF[i][0]; pr.y = aIF[i][1];
            *(ulonglong2*)(myred + 2 * i) = pr;
        }
        __syncthreads();
        ull zIF0 = 0ull, zIF1 = 0ull;
        #pragma unroll
        for (int w8 = 0; w8 < 8; w8++) {
            const ull* pr = red + (w8 * 32 + lane_src) * RED_STRIDE;
            addf2(zIF0, pr[idx0]);
            addf2(zIF1, pr[idx0 + 2]);
        }
        __syncthreads();

        // ---- reduction pass 2: GO ----
        #pragma unroll
        for (int i = 0; i < 8; i++) {
            ulonglong2 pr; pr.x = aGO[i][0]; pr.y = aGO[i][1];
            *(ulonglong2*)(myred + 2 * i) = pr;
        }
        __syncthreads();
        ull zGO0 = 0ull, zGO1 = 0ull;
        #pragma unroll
        for (int w8 = 0; w8 < 8; w8++) {
            const ull* pr = red + (w8 * 32 + lane_src) * RED_STRIDE;
            addf2(zGO0, pr[idx0]);
            addf2(zGO1, pr[idx0 + 2]);
        }

        // ---- activation (rows 2q, 2q+1; hcol jf) ----
        float2 vIF0 = unpack2(zIF0), vGO0 = unpack2(zGO0);
        float2 vIF1 = unpack2(zIF1), vGO1 = unpack2(zGO1);
        float i0 = sigm(vIF0.x + p00), f0 = sigm(vIF0.y + p01);
        float g0 = tanhf(vGO0.x + p02), o0 = sigm(vGO0.y + p03);
        float i1 = sigm(vIF1.x + p10), f1 = sigm(vIF1.y + p11);
        float g1 = tanhf(vGO1.x + p12), o1 = sigm(vGO1.y + p13);
        cs0 = f0 * cs0 + i0 * g0;
        cs1 = f1 * cs1 + i1 * g1;
        float h0 = o0 * tanhf(cs0);
        float h1 = o1 * tanhf(cs1);

        if (t == TT - 1) {
            *(float2*)&g_hfinT[d][ghcol][rb + 2 * q] = make_float2(h0, h1);
        } else {
            const int nb = buf ^ 1;
            *(float2*)&g_hx[gr][nb][ghcol][2 * q] = make_float2(h0, h1);
            __threadfence();
            __syncthreads();
            if (tid == 0) {
                atomicAdd(ctr, 1);
                const int target = 8 * (t + 1);
                while (ld_acq(ctr) < target) { }
            }
            __syncthreads();
            // stage full group h(t) (16 KB) into SMEM buffer nb
            const char* src = (const char*)&g_hx[gr][nb][0][0];
            const uint32_t dbase = hraw_addr + (uint32_t)nb * 16384;
            #pragma unroll
            for (int qq = 0; qq < 4; qq++) {
                int f = tid + qq * 256;
                cpasync16(dbase + (uint32_t)f * 16, src + (size_t)f * 16);
            }
            cp_commit();
        }
    }
}

// =====================================================================
// Kernel C: head.  h1 = relu([hf|hb] @ W1 + b1); out = softmax(h1 @ W2 + b2)
// =====================================================================
__global__ void __launch_bounds__(256) head_kernel(
    const float* __restrict__ W1, const float* __restrict__ b1,
    const float* __restrict__ W2, const float* __restrict__ b2,
    float* __restrict__ out)
{
    __shared__ float hc[8][512];
    __shared__ float h1[8][256];

    const int tid = threadIdx.x;
    const int rb = blockIdx.x * 8;

    for (int i = tid; i < 4096; i += 256) {
        int rr = i >> 9, k = i & 511;
        int dd = k >> 8, kk = k & 255;
        hc[rr][k] = g_hfinT[dd][kk][rb + rr];
    }
    __syncthreads();

    const int jj = tid;
    float acc[8] = {0.f, 0.f, 0.f, 0.f, 0.f, 0.f, 0.f, 0.f};
    for (int k = 0; k < 512; k++) {
        float wv = W1[(size_t)k * HH + jj];
        #pragma unroll
        for (int rr = 0; rr < 8; rr++) acc[rr] += hc[rr][k] * wv;
    }
    float bj = b1[jj];
    #pragma unroll
    for (int rr = 0; rr < 8; rr++) h1[rr][jj] = fmaxf(acc[rr] + bj, 0.f);
    __syncthreads();

    const int rr = tid >> 5, cc = tid & 31;
    float l = b2[cc];
    for (int k = 0; k < HH; k++) l += h1[rr][k] * W2[(size_t)k * NC + cc];

    float m = l;
    #pragma unroll
    for (int o = 16; o > 0; o >>= 1) m = fmaxf(m, __shfl_xor_sync(0xffffffffu, m, o));
    float e = expf(l - m);
    float ssum = e;
    #pragma unroll
    for (int o = 16; o > 0; o >>= 1) ssum += __shfl_xor_sync(0xffffffffu, ssum, o);
    out[(size_t)(rb + rr) * NC + cc] = e / ssum;
}

// =====================================================================
extern "C" void kernel_launch(void* const* d_in, const int* in_sizes, int n_in,
                              void* d_out, int out_size)
{
    const int*   tokens = (const int*)d_in[0];
    const float* emb = (const float*)d_in[1];
    const float* Wf  = (const float*)d_in[2];
    const float* Uf  = (const float*)d_in[3];
    const float* bf  = (const float*)d_in[4];
    const float* Wb  = (const float*)d_in[5];
    const float* Ub  = (const float*)d_in[6];
    const float* bb  = (const float*)d_in[7];
    const float* W1  = (const float*)d_in[8];
    const float* b1  = (const float*)d_in[9];
    const float* W2  = (const float*)d_in[10];
    const float* b2  = (const float*)d_in[11];
    float* out = (float*)d_out;

    cudaFuncSetAttribute(lstm_kernel, cudaFuncAttributeMaxDynamicSharedMemorySize, LSTM_SMEM_BYTES);

    proj_kernel<<<dim3(32, 500), 256>>>(emb, Wf, bf, Wb, bb);
    lstm_kernel<<<128, 256, LSTM_SMEM_BYTES>>>(tokens, Uf, Ub);
    head_kernel<<<16, 256>>>(W1, b1, W2, b2, out);
}

// round 11
// speedup vs baseline: 1.6575x; 1.2154x over previous
#include <cuda_runtime.h>
#include <cstddef>
#include <cstdint>

// Problem constants
#define BB   128     // batch
#define TT   512     // seq len
#define EE   256     // embed dim
#define HH   256     // hidden
#define G4H  1024    // 4*H
#define VV   32000   // vocab
#define NC   32      // classes

typedef unsigned long long ull;

// ---------------- device scratch (no allocations allowed) ----------------
__device__ float g_P[(size_t)VV * 2048];       // [V][2*4H] vocab projection
__device__ float g_hx[16][2][HH][16];          // [group][buf][hcol][row] h exchange
__device__ float g_hfinT[2][HH][BB];           // final hidden per direction, transposed
__device__ int   g_ctr[16 * 32];               // per-group barrier counters (128B apart)

// ---------------- f32x2 helpers ----------------
__device__ __forceinline__ ull pack2(float lo, float hi) {
    ull r;
    asm("mov.b64 %0, {%1, %2};" : "=l"(r) : "f"(lo), "f"(hi));
    return r;
}
__device__ __forceinline__ float2 unpack2(ull v) {
    float2 r;
    asm("mov.b64 {%0, %1}, %2;" : "=f"(r.x), "=f"(r.y) : "l"(v));
    return r;
}
__device__ __forceinline__ void ffma2(ull& d, ull a, ull b) {
    asm("fma.rn.f32x2 %0, %1, %2, %0;" : "+l"(d) : "l"(a), "l"(b));
}
__device__ __forceinline__ void addf2(ull& d, ull a) {
    asm("add.rn.f32x2 %0, %0, %1;" : "+l"(d) : "l"(a));
}

__device__ __forceinline__ int ld_acq(const int* p) {
    int v;
    asm volatile("ld.acquire.gpu.b32 %0, [%1];" : "=r"(v) : "l"(p));
    return v;
}
__device__ __forceinline__ void atom_add_rel(int* p) {
    unsigned int old;
    asm volatile("atom.add.release.gpu.u32 %0, [%1], 1;" : "=r"(old) : "l"(p) : "memory");
}

__device__ __forceinline__ float sigm(float x) { return 1.0f / (1.0f + expf(-x)); }

__device__ __forceinline__ void cpasync16(uint32_t dst, const void* src) {
    asm volatile("cp.async.cg.shared.global [%0], [%1], 16;" :: "r"(dst), "l"(src) : "memory");
}
__device__ __forceinline__ void cp_commit() {
    asm volatile("cp.async.commit_group;" ::: "memory");
}
template<int N> __device__ __forceinline__ void cp_wait() {
    asm volatile("cp.async.wait_group %0;" :: "n"(N) : "memory");
}

// =====================================================================
// Kernel A: P[v, d*1024+g] = sum_e emb[v,e] * W{f,b}[e,g] + b{f,b}[g]
// 2-stage cp.async double buffer (removes exposed DRAM latency per kt tile).
// Also resets group barrier counters for kernel B.
// =====================================================================
__global__ void __launch_bounds__(256) proj_kernel(
    const float* __restrict__ emb,
    const float* __restrict__ Wf, const float* __restrict__ bf,
    const float* __restrict__ Wb, const float* __restrict__ bb)
{
    if (blockIdx.x == 0 && blockIdx.y == 0 && threadIdx.x < 16)
        g_ctr[threadIdx.x * 32] = 0;

    __shared__ float As[2][64][16];   // [stage][m][k] raw A
    __shared__ float Bs[2][16][64];   // [stage][k][n] raw B

    const int tid = threadIdx.x;
    const int tx = tid & 15, ty = tid >> 4;
    const int m0 = ty * 4, n0 = tx * 4;
    const int vbase = blockIdx.y * 64;
    const int nbase = blockIdx.x * 64;
    const int d = nbase >> 10;
    const float* W    = d ? Wb : Wf;
    const float* bias = d ? bb : bf;
    const int gbase = nbase & 1023;

    const uint32_t asA = (uint32_t)__cvta_generic_to_shared(&As[0][0][0]);
    const uint32_t asB = (uint32_t)__cvta_generic_to_shared(&Bs[0][0][0]);

    // per-thread copy coordinates
    const int ar = tid >> 2, aq = tid & 3;     // A: row, k-quad
    const int br = tid >> 4, bsg = tid & 15;   // B: k-row, col-quad

    ull acc[4][2] = {};

    // issue stage 0
    {
        cpasync16(asA + (uint32_t)((ar * 16 + aq * 4) * 4),
                  emb + (size_t)(vbase + ar) * EE + aq * 4);
        cpasync16(asB + (uint32_t)((br * 64 + bsg * 4) * 4),
                  W + (size_t)br * G4H + gbase + bsg * 4);
        cp_commit();
    }

    for (int s = 0; s < 16; s++) {
        if (s + 1 < 16) {
            int b = (s + 1) & 1;
            cpasync16(asA + (uint32_t)(b * 4096 + (ar * 16 + aq * 4) * 4),
                      emb + (size_t)(vbase + ar) * EE + (s + 1) * 16 + aq * 4);
            cpasync16(asB + (uint32_t)(b * 4096 + (br * 64 + bsg * 4) * 4),
                      W + (size_t)((s + 1) * 16 + br) * G4H + gbase + bsg * 4);
            cp_commit();
            cp_wait<1>();     // stage s complete
        } else {
            cp_wait<0>();
        }
        __syncthreads();

        const int b = s & 1;
        #pragma unroll
        for (int k = 0; k < 16; k++) {
            float a0 = As[b][m0 + 0][k];
            float a1 = As[b][m0 + 1][k];
            float a2 = As[b][m0 + 2][k];
            float a3 = As[b][m0 + 3][k];
            ulonglong2 bb2 = *(const ulonglong2*)&Bs[b][k][n0];
            ull ad0 = pack2(a0, a0), ad1 = pack2(a1, a1);
            ull ad2 = pack2(a2, a2), ad3 = pack2(a3, a3);
            ffma2(acc[0][0], ad0, bb2.x); ffma2(acc[0][1], ad0, bb2.y);
            ffma2(acc[1][0], ad1, bb2.x); ffma2(acc[1][1], ad1, bb2.y);
            ffma2(acc[2][0], ad2, bb2.x); ffma2(acc[2][1], ad2, bb2.y);
            ffma2(acc[3][0], ad3, bb2.x); ffma2(acc[3][1], ad3, bb2.y);
        }
        __syncthreads();
    }

    #pragma unroll
    for (int i = 0; i < 4; i++) {
        int v = vbase + m0 + i;
        #pragma unroll
        for (int p = 0; p < 2; p++) {
            float2 va = unpack2(acc[i][p]);
            int cc = n0 + 2 * p;
            va.x += bias[gbase + cc];
            va.y += bias[gbase + cc + 1];
            *(float2*)&g_P[(size_t)v * 2048 + nbase + cc] = va;
        }
    }
}

// =====================================================================
// Kernel B: register-tiled 8-way-k-split LSTM (R10 design + trims):
//  - release-atomic exchange (no per-thread MEMBAR.GPU)
//  - reduction stride 19 (2-way instead of 4-way gather conflicts)
//  - unroll-8 k-loop with loads grouped at block top
// =====================================================================
#define UP_BYTES   131072                     // [256 k][32 hcol] ulonglong2
#define HR_BYTES   32768                      // [2 buf][256 k][16 row] float
#define RED_STRIDE 19                         // ull per thread row (16 + pad)
#define RED_BYTES  (256 * RED_STRIDE * 8)     // 38912
#define LSTM_SMEM_BYTES (UP_BYTES + HR_BYTES + RED_BYTES)   // 202752

__global__ void __launch_bounds__(256) lstm_kernel(
    const int* __restrict__ tokens,
    const float* __restrict__ Uf, const float* __restrict__ Ub)
{
    extern __shared__ char smraw[];
    ulonglong2* Up = (ulonglong2*)smraw;                     // [256 k][32 hcol]
    float* hraw = (float*)(smraw + UP_BYTES);                // [2][256][16]
    ull* red = (ull*)(smraw + UP_BYTES + HR_BYTES);          // [256 thr][19]
    const uint32_t hraw_addr = (uint32_t)__cvta_generic_to_shared(hraw);

    const int tid = threadIdx.x;
    const int gr  = blockIdx.x >> 3;              // group 0..15
    const int c   = blockIdx.x & 7;               // rank in group
    const int d   = gr >> 3;                      // direction
    const int rb  = (gr & 7) * 16;                // batch row base
    const float* U = d ? Ub : Uf;

    const int w    = tid >> 5;                    // warp -> k-slice [32w,32w+32)
    const int lane = tid & 31;
    const int rg   = lane & 1;                    // rows 8rg..8rg+7
    const int cg   = lane >> 1;                   // hcols {cg, cg+16}

    // final-tile identity (post-reduction)
    const int jf = tid & 31;                      // hcol within CTA
    const int q  = tid >> 5;                      // rows {2q, 2q+1}
    const int ghcol = c * 32 + jf;

    // Token dtype guard (jnp.int64 silently x32 in JAX unless x64 enabled).
    const bool is64 = ((tokens[1] | tokens[3] | tokens[5] | tokens[7]) == 0);
    const int ts = is64 ? 2 : 1;

    // Load U: Up[k][j] = { (u_i,u_f), (u_g,u_o) } at hcol c*32+j
    for (int i = tid; i < 8192; i += 256) {
        int k = i >> 5, j = i & 31;
        const float* ub = U + (size_t)k * G4H + c * 32 + j;
        ulonglong2 e;
        e.x = pack2(ub[0],   ub[256]);
        e.y = pack2(ub[512], ub[768]);
        Up[k * 32 + j] = e;
    }
    // zero both h buffers (h(-1) = 0)
    for (int i = tid; i < 8192; i += 256) hraw[i] = 0.f;
    __syncthreads();

    const int* tr0 = tokens + (size_t)(rb + 2 * q + 0) * TT * ts;
    const int* tr1 = tokens + (size_t)(rb + 2 * q + 1) * TT * ts;
    int* ctr = &g_ctr[gr * 32];

    // prefetch tokens for t = 0
    int te0 = d ? (TT - 1) : 0;
    int tk0 = tr0[te0 * ts], tk1 = tr1[te0 * ts];

    float cs0 = 0.f, cs1 = 0.f;

    // gather constants
    const int lane_src = 2 * (jf & 15) + (q >> 2);
    const int idx0 = ((2 * q) & 7) * 2 + (jf >> 4);

    for (int t = 0; t < TT; t++) {
        const int buf = t & 1;

        // ---- P loads for this step (consumed after reduction) ----
        int tv0 = (tk0 >= 0 && tk0 < VV) ? tk0 : 0;
        int tv1 = (tk1 >= 0 && tk1 < VV) ? tk1 : 0;
        const float* Pb0 = g_P + (size_t)tv0 * 2048 + d * 1024 + ghcol;
        const float* Pb1 = g_P + (size_t)tv1 * 2048 + d * 1024 + ghcol;
        float p00 = Pb0[0], p01 = Pb0[256], p02 = Pb0[512], p03 = Pb0[768];
        float p10 = Pb1[0], p11 = Pb1[256], p12 = Pb1[512], p13 = Pb1[768];

        // prefetch tokens for t+1
        if (t + 1 < TT) {
            int te = d ? (TT - 2 - t) : (t + 1);
            tk0 = tr0[te * ts]; tk1 = tr1[te * ts];
        }

        if (t > 0) { cp_wait<0>(); __syncthreads(); }   // h(t-1) staged

        // ---- k-loop over this warp's 32-k slice ----
        const float* hb = hraw + buf * 4096;
        const ulonglong2* ub2 = Up + cg;
        ull aIF[8][2] = {}, aGO[8][2] = {};
        const int kbeg = w * 32;
        #pragma unroll 8
        for (int k = kbeg; k < kbeg + 32; k++) {
            float4 hA = *(const float4*)(hb + k * 16 + 8 * rg);
            float4 hB = *(const float4*)(hb + k * 16 + 8 * rg + 4);
            ulonglong2 uA = ub2[k * 32];         // hcol cg
            ulonglong2 uB = ub2[k * 32 + 16];    // hcol cg+16
            ull hd0 = pack2(hA.x, hA.x), hd1 = pack2(hA.y, hA.y);
            ull hd2 = pack2(hA.z, hA.z), hd3 = pack2(hA.w, hA.w);
            ull hd4 = pack2(hB.x, hB.x), hd5 = pack2(hB.y, hB.y);
            ull hd6 = pack2(hB.z, hB.z), hd7 = pack2(hB.w, hB.w);
            ffma2(aIF[0][0], hd0, uA.x); ffma2(aGO[0][0], hd0, uA.y);
            ffma2(aIF[0][1], hd0, uB.x); ffma2(aGO[0][1], hd0, uB.y);
            ffma2(aIF[1][0], hd1, uA.x); ffma2(aGO[1][0], hd1, uA.y);
            ffma2(aIF[1][1], hd1, uB.x); ffma2(aGO[1][1], hd1, uB.y);
            ffma2(aIF[2][0], hd2, uA.x); ffma2(aGO[2][0], hd2, uA.y);
            ffma2(aIF[2][1], hd2, uB.x); ffma2(aGO[2][1], hd2, uB.y);
            ffma2(aIF[3][0], hd3, uA.x); ffma2(aGO[3][0], hd3, uA.y);
            ffma2(aIF[3][1], hd3, uB.x); ffma2(aGO[3][1], hd3, uB.y);
            ffma2(aIF[4][0], hd4, uA.x); ffma2(aGO[4][0], hd4, uA.y);
            ffma2(aIF[4][1], hd4, uB.x); ffma2(aGO[4][1], hd4, uB.y);
            ffma2(aIF[5][0], hd5, uA.x); ffma2(aGO[5][0], hd5, uA.y);
            ffma2(aIF[5][1], hd5, uB.x); ffma2(aGO[5][1], hd5, uB.y);
            ffma2(aIF[6][0], hd6, uA.x); ffma2(aGO[6][0], hd6, uA.y);
            ffma2(aIF[6][1], hd6, uB.x); ffma2(aGO[6][1], hd6, uB.y);
            ffma2(aIF[7][0], hd7, uA.x); ffma2(aGO[7][0], hd7, uA.y);
            ffma2(aIF[7][1], hd7, uB.x); ffma2(aGO[7][1], hd7, uB.y);
        }

        ull* myred = red + tid * RED_STRIDE;

        // ---- reduction pass 1: IF ----
        #pragma unroll
        for (int i = 0; i < 8; i++) {
            myred[2 * i]     = aIF[i][0];
            myred[2 * i + 1] = aIF[i][1];
        }
        __syncthreads();
        ull zIF0 = 0ull, zIF1 = 0ull;
        #pragma unroll
        for (int w8 = 0; w8 < 8; w8++) {
            const ull* pr = red + (w8 * 32 + lane_src) * RED_STRIDE;
            addf2(zIF0, pr[idx0]);
            addf2(zIF1, pr[idx0 + 2]);
        }
        __syncthreads();

        // ---- reduction pass 2: GO ----
        #pragma unroll
        for (int i = 0; i < 8; i++) {
            myred[2 * i]     = aGO[i][0];
            myred[2 * i + 1] = aGO[i][1];
        }
        __syncthreads();
        ull zGO0 = 0ull, zGO1 = 0ull;
        #pragma unroll
        for (int w8 = 0; w8 < 8; w8++) {
            const ull* pr = red + (w8 * 32 + lane_src) * RED_STRIDE;
            addf2(zGO0, pr[idx0]);
            addf2(zGO1, pr[idx0 + 2]);
        }

        // ---- activation (rows 2q, 2q+1; hcol jf) ----
        float2 vIF0 = unpack2(zIF0), vGO0 = unpack2(zGO0);
        float2 vIF1 = unpack2(zIF1), vGO1 = unpack2(zGO1);
        float i0 = sigm(vIF0.x + p00), f0 = sigm(vIF0.y + p01);
        float g0 = tanhf(vGO0.x + p02), o0 = sigm(vGO0.y + p03);
        float i1 = sigm(vIF1.x + p10), f1 = sigm(vIF1.y + p11);
        float g1 = tanhf(vGO1.x + p12), o1 = sigm(vGO1.y + p13);
        cs0 = f0 * cs0 + i0 * g0;
        cs1 = f1 * cs1 + i1 * g1;
        float h0 = o0 * tanhf(cs0);
        float h1 = o1 * tanhf(cs1);

        if (t == TT - 1) {
            *(float2*)&g_hfinT[d][ghcol][rb + 2 * q] = make_float2(h0, h1);
        } else {
            const int nb = buf ^ 1;
            *(float2*)&g_hx[gr][nb][ghcol][2 * q] = make_float2(h0, h1);
            __syncthreads();                       // all CTA stores issued
            if (tid == 0) {
                atom_add_rel(ctr);                 // release: publishes CTA's h
                const int target = 8 * (t + 1);
                while (ld_acq(ctr) < target) { }
            }
            __syncthreads();
            // stage full group h(t) (16 KB) into SMEM buffer nb
            const char* src = (const char*)&g_hx[gr][nb][0][0];
            const uint32_t dbase = hraw_addr + (uint32_t)nb * 16384;
            #pragma unroll
            for (int qq = 0; qq < 4; qq++) {
                int f = tid + qq * 256;
                cpasync16(dbase + (uint32_t)f * 16, src + (size_t)f * 16);
            }
            cp_commit();
        }
    }
}

// =====================================================================
// Kernel C: head.  h1 = relu([hf|hb] @ W1 + b1); out = softmax(h1 @ W2 + b2)
// =====================================================================
__global__ void __launch_bounds__(256) head_kernel(
    const float* __restrict__ W1, const float* __restrict__ b1,
    const float* __restrict__ W2, const float* __restrict__ b2,
    float* __restrict__ out)
{
    __shared__ float hc[8][512];
    __shared__ float h1[8][256];

    const int tid = threadIdx.x;
    const int rb = blockIdx.x * 8;

    for (int i = tid; i < 4096; i += 256) {
        int rr = i >> 9, k = i & 511;
        int dd = k >> 8, kk = k & 255;
        hc[rr][k] = g_hfinT[dd][kk][rb + rr];
    }
    __syncthreads();

    const int jj = tid;
    float acc[8] = {0.f, 0.f, 0.f, 0.f, 0.f, 0.f, 0.f, 0.f};
    for (int k = 0; k < 512; k++) {
        float wv = W1[(size_t)k * HH + jj];
        #pragma unroll
        for (int rr = 0; rr < 8; rr++) acc[rr] += hc[rr][k] * wv;
    }
    float bj = b1[jj];
    #pragma unroll
    for (int rr = 0; rr < 8; rr++) h1[rr][jj] = fmaxf(acc[rr] + bj, 0.f);
    __syncthreads();

    const int rr = tid >> 5, cc = tid & 31;
    float l = b2[cc];
    for (int k = 0; k < HH; k++) l += h1[rr][k] * W2[(size_t)k * NC + cc];

    float m = l;
    #pragma unroll
    for (int o = 16; o > 0; o >>= 1) m = fmaxf(m, __shfl_xor_sync(0xffffffffu, m, o));
    float e = expf(l - m);
    float ssum = e;
    #pragma unroll
    for (int o = 16; o > 0; o >>= 1) ssum += __shfl_xor_sync(0xffffffffu, ssum, o);
    out[(size_t)(rb + rr) * NC + cc] = e / ssum;
}

// =====================================================================
extern "C" void kernel_launch(void* const* d_in, const int* in_sizes, int n_in,
                              void* d_out, int out_size)
{
    const int*   tokens = (const int*)d_in[0];
    const float* emb = (const float*)d_in[1];
    const float* Wf  = (const float*)d_in[2];
    const float* Uf  = (const float*)d_in[3];
    const float* bf  = (const float*)d_in[4];
    const float* Wb  = (const float*)d_in[5];
    const float* Ub  = (const float*)d_in[6];
    const float* bb  = (const float*)d_in[7];
    const float* W1  = (const float*)d_in[8];
    const float* b1  = (const float*)d_in[9];
    const float* W2  = (const float*)d_in[10];
    const float* b2  = (const float*)d_in[11];
    float* out = (float*)d_out;

    cudaFuncSetAttribute(lstm_kernel, cudaFuncAttributeMaxDynamicSharedMemorySize, LSTM_SMEM_BYTES);

    proj_kernel<<<dim3(32, 500), 256>>>(emb, Wf, bf, Wb, bb);
    lstm_kernel<<<128, 256, LSTM_SMEM_BYTES>>>(tokens, Uf, Ub);
    head_kernel<<<16, 256>>>(W1, b1, W2, b2, out);
}